// round 5
// baseline (speedup 1.0000x reference)
#include <cuda_runtime.h>

#define BATCH 16384
#define LSEQ  256
#define CH    32
#define EPSBN 1e-5
#define LOG2PI 1.8378770664093453f

typedef unsigned long long ull;

// ---------------- scratch (device-global; no runtime alloc allowed) -------
__device__ float  g_buf1[(size_t)BATCH*CH*LSEQ];   // conv1 output (pre-BN)
__device__ float  g_buf2[(size_t)BATCH*CH*LSEQ];   // h1 then h2 (pre-BN)
__device__ float  g_ctx [(size_t)BATCH*64];        // context vectors
__device__ double g_stat[3][2][32];                // [stage][sum|sumsq][channel]

// ---------------- packed fp32x2 helpers (FFMA2) ----------------------------
__device__ __forceinline__ ull pk(float lo, float hi){
    ull r; asm("mov.b64 %0, {%1,%2};" : "=l"(r) : "f"(lo), "f"(hi)); return r;
}
__device__ __forceinline__ void upk(ull v, float& lo, float& hi){
    asm("mov.b64 {%0,%1}, %2;" : "=f"(lo), "=f"(hi) : "l"(v));
}
// in-place accumulate: a = b*c + a   (keeps ptxas from inserting pair moves)
__device__ __forceinline__ void ffma2_acc(ull& a, ull b, ull c){
    asm("fma.rn.f32x2 %0, %1, %2, %0;" : "+l"(a) : "l"(b), "l"(c));
}
__device__ __forceinline__ ull ffma2(ull a, ull b, ull c){
    ull d; asm("fma.rn.f32x2 %0, %1, %2, %3;" : "=l"(d) : "l"(a), "l"(b), "l"(c)); return d;
}

__device__ __forceinline__ float wred32(float v){
#pragma unroll
    for (int o = 16; o > 0; o >>= 1) v += __shfl_xor_sync(0xffffffffu, v, o);
    return v;
}

// ---------------- K0: zero the stat accumulators ---------------------------
__global__ void k_init_stats(){
    int t = threadIdx.x;
    if (t < 192) (&g_stat[0][0][0])[t] = 0.0;
}

// ---------------- K1: conv1 (4->32, k=5, SAME) + bias, stats stage 0 -------
// warp -> 8 channels; lane -> 4 packed L-pairs (l, l+128); pre-paired input
__global__ __launch_bounds__(128) void k_conv1(const float* __restrict__ curve,
                                               const float* __restrict__ w,
                                               const float* __restrict__ bias){
    const int b = blockIdx.x;
    const int t = threadIdx.x;
    extern __shared__ ull smu[];
    ull*   wd  = smu;                     // dup weights: ull[(i*32+c)*8 + k], 1024 (k<5 live)
    ull*   xpd = wd + 1024;               // pre-paired input: [4][132], xpd[i][p]=(x[p-2],x[p+126])
    float* cbs = (float*)(xpd + 4*132);   // 32
    float* redS= cbs + 32;                // 32
    float* redQ= redS + 32;               // 32

    if (t < 32) cbs[t] = bias[t];
    for (int idx = t; idx < 4*32*8; idx += 128){
        int i = idx >> 8, rem = idx & 255, c = rem >> 3, k = rem & 7;
        float v = (k < 5) ? w[c*20 + i*5 + k] : 0.f;
        ((float2*)wd)[idx] = make_float2(v, v);
    }
    for (int idx = t; idx < 4*132; idx += 128){
        int i = idx / 132, p = idx - i*132;
        int p0 = p - 2, p1 = p + 126;
        const float* src = curve + ((size_t)b*4 + i)*LSEQ;
        float v0 = (p0 >= 0 && p0 < LSEQ) ? src[p0] : 0.f;
        float v1 = (p1 < LSEQ) ? src[p1] : 0.f;
        xpd[idx] = pk(v0, v1);
    }
    __syncthreads();

    const int wrp = t >> 5, lane = t & 31;
    const int c0 = wrp*8, l0 = lane*4;

    ull A[8][4];
#pragma unroll
    for (int cc = 0; cc < 8; cc++){
        float cb = cbs[c0 + cc];
#pragma unroll
        for (int j = 0; j < 4; j++) A[cc][j] = pk(cb, cb);
    }

#pragma unroll
    for (int i = 0; i < 4; i++){
        const ull* xb = xpd + i*132 + l0;      // xb[m] = (x_{l0+m-2}, x_{l0+m+126})
        ulonglong2 q0 = *(const ulonglong2*)(xb);
        ulonglong2 q1 = *(const ulonglong2*)(xb + 2);
        ulonglong2 q2 = *(const ulonglong2*)(xb + 4);
        ulonglong2 q3 = *(const ulonglong2*)(xb + 6);
        ull P[8] = {q0.x,q0.y, q1.x,q1.y, q2.x,q2.y, q3.x,q3.y};
        const ull* wp = wd + (i*32 + c0)*8;
#pragma unroll
        for (int cc = 0; cc < 8; cc++){
            ulonglong2 W01 = *(const ulonglong2*)(wp + cc*8);
            ulonglong2 W23 = *(const ulonglong2*)(wp + cc*8 + 2);
            ull W4 = wp[cc*8 + 4];
#pragma unroll
            for (int j = 0; j < 4; j++){
                ffma2_acc(A[cc][j], P[j+0], W01.x);
                ffma2_acc(A[cc][j], P[j+1], W01.y);
                ffma2_acc(A[cc][j], P[j+2], W23.x);
                ffma2_acc(A[cc][j], P[j+3], W23.y);
                ffma2_acc(A[cc][j], P[j+4], W4);
            }
        }
    }

    float* outp = g_buf1 + (size_t)b*CH*LSEQ;
#pragma unroll
    for (int cc = 0; cc < 8; cc++){
        float vl[4], vh[4];
#pragma unroll
        for (int j = 0; j < 4; j++) upk(A[cc][j], vl[j], vh[j]);
        int c = c0 + cc;
        *(float4*)(outp + c*LSEQ + l0)       = make_float4(vl[0],vl[1],vl[2],vl[3]);
        *(float4*)(outp + c*LSEQ + l0 + 128) = make_float4(vh[0],vh[1],vh[2],vh[3]);
        float s = 0.f, q = 0.f;
#pragma unroll
        for (int m = 0; m < 4; m++){ s += vl[m] + vh[m]; q += vl[m]*vl[m] + vh[m]*vh[m]; }
        s = wred32(s); q = wred32(q);
        if (lane == 0){ redS[c] = s; redQ[c] = q; }   // channel owned by one warp
    }
    __syncthreads();
    if (t < 32){
        atomicAdd(&g_stat[0][0][t], (double)redS[t]);
        atomicAdd(&g_stat[0][1][t], (double)redQ[t]);
    }
}

// ---------------- K2/K3: bn+relu(in) -> conv (32->32, k=3, SAME)+bias ------
// warp -> 8 channels; lane -> 4 packed L-pairs (l, l+128); pre-paired input
__global__ __launch_bounds__(128) void k_rbconv(int pass,
                                                const float* __restrict__ gam,
                                                const float* __restrict__ bet,
                                                const float* __restrict__ w,
                                                const float* __restrict__ cbias){
    const int b = blockIdx.x;
    const int t = threadIdx.x;
    const float* bufIn = (pass == 0) ? g_buf1 : g_buf2;
    float* bufOut = g_buf2;
    const int stIn = pass, stOut = pass + 1;

    extern __shared__ ull smu[];
    ull*   wd  = smu;                     // dup weights: ull[(i*32+c)*4 + k], 4096 (k<3 live)
    ull*   xpd = wd + 4096;               // pre-paired: [32][130], xpd[i][p]=(xr[p-1],xr[p+127])
    float* sc  = (float*)(xpd + 32*130);  // 32
    float* sh  = sc + 32;                 // 32
    float* cbs = sh + 32;                 // 32
    float* redS= cbs + 32;                // 32
    float* redQ= redS + 32;               // 32

    if (t < 32){
        const double N = (double)BATCH * (double)LSEQ;
        double S = g_stat[stIn][0][t], Q = g_stat[stIn][1][t];
        double m = S / N, v = Q / N - m*m;
        double s = (double)gam[t] / sqrt(v + EPSBN);
        sc[t] = (float)s;
        sh[t] = (float)((double)bet[t] - m*s);
        cbs[t] = cbias[t];
    }
    for (int idx = t; idx < 32*32*4; idx += 128){
        int i = idx >> 7, rem = idx & 127, c = rem >> 2, k = rem & 3;
        float v = (k < 3) ? w[c*96 + i*3 + k] : 0.f;
        ((float2*)wd)[idx] = make_float2(v, v);
    }
    __syncthreads();

    const float* inp = bufIn + (size_t)b*CH*LSEQ;
    for (int idx = t; idx < 32*130; idx += 128){
        int i = idx / 130, p = idx - i*130;
        int p0 = p - 1, p1 = p + 127;
        float sci = sc[i], shi = sh[i];
        float v0 = (p0 >= 0) ? fmaxf(sci*inp[i*LSEQ + p0] + shi, 0.f) : 0.f;
        float v1 = (p1 < LSEQ) ? fmaxf(sci*inp[i*LSEQ + p1] + shi, 0.f) : 0.f;
        xpd[idx] = pk(v0, v1);
    }
    __syncthreads();

    const int wrp = t >> 5, lane = t & 31;
    const int c0 = wrp*8, l0 = lane*4;

    ull A[8][4];
#pragma unroll
    for (int cc = 0; cc < 8; cc++){
        float cb = cbs[c0 + cc];
#pragma unroll
        for (int j = 0; j < 4; j++) A[cc][j] = pk(cb, cb);
    }

#pragma unroll 4
    for (int i = 0; i < 32; i++){
        const ull* xb = xpd + i*130 + l0;      // xb[m] = (xr_{l0+m-1}, xr_{l0+m+127})
        ulonglong2 q0 = *(const ulonglong2*)(xb);
        ulonglong2 q1 = *(const ulonglong2*)(xb + 2);
        ulonglong2 q2 = *(const ulonglong2*)(xb + 4);
        ull P[6] = {q0.x, q0.y, q1.x, q1.y, q2.x, q2.y};
        const ull* wp = wd + (i*32 + c0)*4;
#pragma unroll
        for (int cc = 0; cc < 8; cc++){
            ulonglong2 W01 = *(const ulonglong2*)(wp + cc*4);
            ull W2 = wp[cc*4 + 2];
#pragma unroll
            for (int j = 0; j < 4; j++){
                ffma2_acc(A[cc][j], P[j+0], W01.x);
                ffma2_acc(A[cc][j], P[j+1], W01.y);
                ffma2_acc(A[cc][j], P[j+2], W2);
            }
        }
    }

    float* outp = bufOut + (size_t)b*CH*LSEQ;
#pragma unroll
    for (int cc = 0; cc < 8; cc++){
        float vl[4], vh[4];
#pragma unroll
        for (int j = 0; j < 4; j++) upk(A[cc][j], vl[j], vh[j]);
        int c = c0 + cc;
        *(float4*)(outp + c*LSEQ + l0)       = make_float4(vl[0],vl[1],vl[2],vl[3]);
        *(float4*)(outp + c*LSEQ + l0 + 128) = make_float4(vh[0],vh[1],vh[2],vh[3]);
        float s = 0.f, q = 0.f;
#pragma unroll
        for (int m = 0; m < 4; m++){ s += vl[m] + vh[m]; q += vl[m]*vl[m] + vh[m]*vh[m]; }
        s = wred32(s); q = wred32(q);
        if (lane == 0){ redS[c] = s; redQ[c] = q; }
    }
    __syncthreads();
    if (t < 32){
        atomicAdd(&g_stat[stOut][0][t], (double)redS[t]);
        atomicAdd(&g_stat[stOut][1][t], (double)redQ[t]);
    }
}

// ---------------- K4: bn0+relu, bn2, residual+relu, mean-pool, linear+tanh -
__global__ __launch_bounds__(256) void k_pool_ctx(const float* __restrict__ gamma1,
                                                  const float* __restrict__ beta1,
                                                  const float* __restrict__ gamma3,
                                                  const float* __restrict__ beta3,
                                                  const float* __restrict__ lin_w,
                                                  const float* __restrict__ lin_b){
    const int b = blockIdx.x;
    const int t = threadIdx.x;
    __shared__ float sc0[32], sh0[32], sc2[32], sh2[32];
    __shared__ float red[32][8];
    __shared__ float pooled[32];

    if (t < 32){
        const double N = (double)BATCH * (double)LSEQ;
        { double S = g_stat[0][0][t], Q = g_stat[0][1][t];
          double m = S/N, v = Q/N - m*m;
          double s = (double)gamma1[t] / sqrt(v + EPSBN);
          sc0[t] = (float)s; sh0[t] = (float)((double)beta1[t] - m*s); }
        { double S = g_stat[2][0][t], Q = g_stat[2][1][t];
          double m = S/N, v = Q/N - m*m;
          double s = (double)gamma3[t] / sqrt(v + EPSBN);
          sc2[t] = (float)s; sh2[t] = (float)((double)beta3[t] - m*s); }
    }
    __syncthreads();

    const float* p1 = g_buf1 + (size_t)b*CH*LSEQ;
    const float* p2 = g_buf2 + (size_t)b*CH*LSEQ;
    const int wid = t >> 5, lane = t & 31;
#pragma unroll 1
    for (int c = 0; c < 32; c++){
        float y1 = p1[c*LSEQ + t];
        float h2 = p2[c*LSEQ + t];
        float x1 = fmaxf(sc0[c]*y1 + sh0[c], 0.f);
        float x2 = fmaxf(sc2[c]*h2 + sh2[c] + x1, 0.f);
        float s = wred32(x2);
        if (lane == 0) red[c][wid] = s;
    }
    __syncthreads();
    if (t < 32){
        float s = 0.f;
#pragma unroll
        for (int wI = 0; wI < 8; wI++) s += red[t][wI];
        pooled[t] = s * (1.f/(float)LSEQ);
    }
    __syncthreads();
    if (t < 64){
        float acc = lin_b[t];
#pragma unroll
        for (int c = 0; c < 32; c++) acc += pooled[c]*lin_w[c*64 + t];
        g_ctx[(size_t)b*64 + t] = tanhf(acc);
    }
}

// ---------------- K5: 10 coupling layers, 64 rows per block, all in smem ---
__global__ __launch_bounds__(256) void k_coupling(const float* __restrict__ zin,
                                                  const float* __restrict__ W1,
                                                  const float* __restrict__ B1,
                                                  const float* __restrict__ W2,
                                                  const float* __restrict__ B2,
                                                  const float* __restrict__ W3,
                                                  const float* __restrict__ B3,
                                                  float* __restrict__ outp){
    const int t = threadIdx.x;
    const int rowBase = blockIdx.x * 64;
    extern __shared__ float sm[];
    float* nin = sm;                 // 64*76  (cols 0..8 = z*mask, 9..72 = ctx)
    float* hA  = nin + 64*76;        // 64*132
    float* hB  = hA  + 64*132;       // 64*132
    float* zz  = hB  + 64*132;       // 64*12
    float* ob  = zz  + 64*12;        // 64*20
    float* ldv = ob  + 64*20;        // 64

    for (int idx = t; idx < 64*9; idx += 256){
        int r = idx/9, j = idx - r*9;
        zz[r*12 + j] = zin[(size_t)(rowBase + r)*9 + j];
    }
    for (int idx = t; idx < 64*64; idx += 256){
        int r = idx >> 6, j = idx & 63;
        nin[r*76 + 9 + j] = g_ctx[(size_t)(rowBase + r)*64 + j];
    }
    if (t < 64) ldv[t] = 0.f;
    __syncthreads();

    const int jc = t & 31;           // 4 output columns: 4*jc .. 4*jc+3
    const int r0 = (t >> 5) * 8;     // 8 rows per warp

    for (int layer = 0; layer < 10; ++layer){
        if (t < 64){
#pragma unroll
            for (int j = 0; j < 9; j++){
                float m = (((j + layer) & 1) == 0) ? 1.f : 0.f;
                nin[t*76 + j] = zz[t*12 + j] * m;
            }
        }
        __syncthreads();

        // GEMM1: hA = relu(nin[64x73] @ W1[73x128] + b1)  (packed f32x2)
        {
            const float* Wl = W1 + (size_t)layer*73*128;
            float4 bb = *(const float4*)(B1 + layer*128 + 4*jc);
            ull acc[8][2];
#pragma unroll
            for (int r = 0; r < 8; r++){ acc[r][0] = pk(bb.x, bb.y); acc[r][1] = pk(bb.z, bb.w); }
#pragma unroll 2
            for (int i = 0; i < 73; i++){
                ulonglong2 wv = *(const ulonglong2*)(Wl + i*128 + 4*jc);
#pragma unroll
                for (int r = 0; r < 8; r++){
                    float x = nin[(r0 + r)*76 + i];
                    ull xx = pk(x, x);
                    ffma2_acc(acc[r][0], xx, wv.x);
                    ffma2_acc(acc[r][1], xx, wv.y);
                }
            }
#pragma unroll
            for (int r = 0; r < 8; r++){
                float v0,v1,v2,v3;
                upk(acc[r][0], v0, v1); upk(acc[r][1], v2, v3);
                *(float4*)(hA + (r0 + r)*132 + 4*jc) =
                    make_float4(fmaxf(v0,0.f), fmaxf(v1,0.f), fmaxf(v2,0.f), fmaxf(v3,0.f));
            }
        }
        __syncthreads();

        // GEMM2: hB = relu(hA[64x128] @ W2[128x128] + b2)  (packed f32x2)
        {
            const float* Wl = W2 + (size_t)layer*128*128;
            float4 bb = *(const float4*)(B2 + layer*128 + 4*jc);
            ull acc[8][2];
#pragma unroll
            for (int r = 0; r < 8; r++){ acc[r][0] = pk(bb.x, bb.y); acc[r][1] = pk(bb.z, bb.w); }
#pragma unroll 2
            for (int i = 0; i < 128; i++){
                ulonglong2 wv = *(const ulonglong2*)(Wl + i*128 + 4*jc);
#pragma unroll
                for (int r = 0; r < 8; r++){
                    float x = hA[(r0 + r)*132 + i];
                    ull xx = pk(x, x);
                    ffma2_acc(acc[r][0], xx, wv.x);
                    ffma2_acc(acc[r][1], xx, wv.y);
                }
            }
#pragma unroll
            for (int r = 0; r < 8; r++){
                float v0,v1,v2,v3;
                upk(acc[r][0], v0, v1); upk(acc[r][1], v2, v3);
                *(float4*)(hB + (r0 + r)*132 + 4*jc) =
                    make_float4(fmaxf(v0,0.f), fmaxf(v1,0.f), fmaxf(v2,0.f), fmaxf(v3,0.f));
            }
        }
        __syncthreads();

        // GEMM3: ob = hB[64x128] @ W3[128x18] + b3
        {
            const float* Wl = W3 + (size_t)layer*128*18;
            const int r = t >> 2, q = t & 3;
            float acc[5] = {0.f,0.f,0.f,0.f,0.f};
#pragma unroll 2
            for (int i = 0; i < 128; i++){
                float x = hB[r*132 + i];
#pragma unroll
                for (int k = 0; k < 5; k++){
                    int j = q + 4*k;
                    if (j < 18) acc[k] = fmaf(x, __ldg(Wl + i*18 + j), acc[k]);
                }
            }
#pragma unroll
            for (int k = 0; k < 5; k++){
                int j = q + 4*k;
                if (j < 18) ob[r*20 + j] = acc[k] + B3[layer*18 + j];
            }
        }
        __syncthreads();

        // per-row flow update
        if (t < 64){
            float ldl = ldv[t];
#pragma unroll
            for (int j = 0; j < 9; j++){
                if (((j + layer) & 1) != 0){     // unmasked dims
                    float s  = tanhf(ob[t*20 + j]);
                    float tt = ob[t*20 + 9 + j];
                    zz[t*12 + j] = zz[t*12 + j]*expf(s) + tt;
                    ldl += s;
                }
            }
            ldv[t] = ldl;
        }
        __syncthreads();
    }

    if (t < 64){
        float lp = 0.f;
#pragma unroll
        for (int j = 0; j < 9; j++){
            float z = zz[t*12 + j];
            lp += LOG2PI + z*z;
        }
        outp[rowBase + t] = ldv[t] - 0.5f*lp;
    }
}

// ---------------- launch ----------------------------------------------------
extern "C" void kernel_launch(void* const* d_in, const int* in_sizes, int n_in,
                              void* d_out, int out_size){
    const float* inputs  = (const float*)d_in[0];
    const float* curve   = (const float*)d_in[1];
    const float* conv1_w = (const float*)d_in[2];
    const float* conv1_b = (const float*)d_in[3];
    const float* bn1_g   = (const float*)d_in[4];
    const float* bn1_b   = (const float*)d_in[5];
    const float* rb_w1   = (const float*)d_in[6];
    const float* rb_b1   = (const float*)d_in[7];
    const float* rb_g1   = (const float*)d_in[8];
    const float* rb_be1  = (const float*)d_in[9];
    const float* rb_w2   = (const float*)d_in[10];
    const float* rb_b2   = (const float*)d_in[11];
    const float* rb_g2   = (const float*)d_in[12];
    const float* rb_be2  = (const float*)d_in[13];
    const float* lin_w   = (const float*)d_in[14];
    const float* lin_b   = (const float*)d_in[15];
    const float* W1      = (const float*)d_in[16];
    const float* B1      = (const float*)d_in[17];
    const float* W2      = (const float*)d_in[18];
    const float* B2      = (const float*)d_in[19];
    const float* W3      = (const float*)d_in[20];
    const float* B3      = (const float*)d_in[21];
    float* out = (float*)d_out;

    const int smem1 = 1024*8 + 4*132*8 + (32 + 64) * 4;
    const int smemR = 4096*8 + 32*130*8 + (96 + 64) * 4;
    const int smemC = (64*76 + 64*132*2 + 64*12 + 64*20 + 64) * 4;

    cudaFuncSetAttribute(k_conv1,    cudaFuncAttributeMaxDynamicSharedMemorySize, smem1);
    cudaFuncSetAttribute(k_rbconv,   cudaFuncAttributeMaxDynamicSharedMemorySize, smemR);
    cudaFuncSetAttribute(k_coupling, cudaFuncAttributeMaxDynamicSharedMemorySize, smemC);

    k_init_stats<<<1, 192>>>();
    k_conv1<<<BATCH, 128, smem1>>>(curve, conv1_w, conv1_b);
    k_rbconv<<<BATCH, 128, smemR>>>(0, bn1_g, bn1_b, rb_w1, rb_b1);
    k_rbconv<<<BATCH, 128, smemR>>>(1, rb_g1, rb_be1, rb_w2, rb_b2);
    k_pool_ctx<<<BATCH, 256>>>(bn1_g, bn1_b, rb_g2, rb_be2, lin_w, lin_b);
    k_coupling<<<BATCH/64, 256, smemC>>>(inputs, W1, B1, W2, B2, W3, B3, out);
}

// round 6
// speedup vs baseline: 1.2694x; 1.2694x over previous
#include <cuda_runtime.h>

#define BATCH 16384
#define LSEQ  256
#define CH    32
#define EPSBN 1e-5
#define LOG2PI 1.8378770664093453f

typedef unsigned long long ull;

// ---------------- scratch (device-global; no runtime alloc allowed) -------
__device__ float  g_buf1[(size_t)BATCH*CH*LSEQ];   // conv1 output (pre-BN)
__device__ float  g_buf2[(size_t)BATCH*CH*LSEQ];   // h1 then h2 (pre-BN)
__device__ float  g_ctx [(size_t)BATCH*64];        // context vectors
__device__ double g_stat[3][2][32];                // [stage][sum|sumsq][channel]

// ---------------- packed fp32x2 helpers (FFMA2) ----------------------------
__device__ __forceinline__ ull pk(float lo, float hi){
    ull r; asm("mov.b64 %0, {%1,%2};" : "=l"(r) : "f"(lo), "f"(hi)); return r;
}
__device__ __forceinline__ void upk(ull v, float& lo, float& hi){
    asm("mov.b64 {%0,%1}, %2;" : "=f"(lo), "=f"(hi) : "l"(v));
}
__device__ __forceinline__ void ffma2_acc(ull& a, ull b, ull c){
    asm("fma.rn.f32x2 %0, %1, %2, %0;" : "+l"(a) : "l"(b), "l"(c));
}

__device__ __forceinline__ float wred32(float v){
#pragma unroll
    for (int o = 16; o > 0; o >>= 1) v += __shfl_xor_sync(0xffffffffu, v, o);
    return v;
}

// ---------------- K0: zero the stat accumulators ---------------------------
__global__ void k_init_stats(){
    int t = threadIdx.x;
    if (t < 192) (&g_stat[0][0][0])[t] = 0.0;
}

// ---------------- K1: conv1 (4->32, k=5, SAME) + bias, stats stage 0 -------
// warp -> 8 output channels (broadcast weights); lane -> 8 L positions
__global__ __launch_bounds__(128) void k_conv1(const float* __restrict__ curve,
                                               const float* __restrict__ w,
                                               const float* __restrict__ bias){
    const int b = blockIdx.x;
    const int t = threadIdx.x;
    extern __shared__ ull smu[];
    ull*   wd  = smu;                     // dup weights: ull[(i*32+c)*8 + k], 1024 (k<5 live)
    float* cbs = (float*)(wd + 1024);     // 32
    float* xin = cbs + 32;                // 4*272 (xin[i][l+2])
    float* redS= xin + 4*272;             // 32
    float* redQ= redS + 32;               // 32

    if (t < 32) cbs[t] = bias[t];
    for (int idx = t; idx < 4*272; idx += 128){
        int i = idx / 272, p = idx - i*272, l = p - 2;
        xin[idx] = (l >= 0 && l < LSEQ) ? curve[((size_t)b*4 + i)*LSEQ + l] : 0.f;
    }
    for (int idx = t; idx < 4*32*8; idx += 128){
        int i = idx >> 8, rem = idx & 255, c = rem >> 3, k = rem & 7;
        float v = (k < 5) ? w[c*20 + i*5 + k] : 0.f;
        ((float2*)wd)[idx] = make_float2(v, v);
    }
    __syncthreads();

    const int wrp = t >> 5, lane = t & 31;
    const int c0 = wrp*8, l0 = lane*8;

    ull A[8][4];
#pragma unroll
    for (int cc = 0; cc < 8; cc++){
        float cb = cbs[c0 + cc];
#pragma unroll
        for (int p = 0; p < 4; p++) A[cc][p] = pk(cb, cb);
    }

#pragma unroll
    for (int i = 0; i < 4; i++){
        const float* xb = xin + i*272 + l0;        // xb[0] = x_{l0-2}
        float4 u0 = *(const float4*)(xb);
        float4 u1 = *(const float4*)(xb + 4);
        float4 u2 = *(const float4*)(xb + 8);
        float xm[12] = {u0.x,u0.y,u0.z,u0.w, u1.x,u1.y,u1.z,u1.w, u2.x,u2.y,u2.z,u2.w};
        ull P[11];
#pragma unroll
        for (int m = 0; m < 11; m++) P[m] = pk(xm[m], xm[m+1]);   // (x_{l0+m-2}, x_{l0+m-1})
        const ull* wp = wd + (i*32 + c0)*8;
#pragma unroll
        for (int cc = 0; cc < 8; cc++){
            ulonglong2 W01 = *(const ulonglong2*)(wp + cc*8);
            ulonglong2 W23 = *(const ulonglong2*)(wp + cc*8 + 2);
            ull W4 = wp[cc*8 + 4];
#pragma unroll
            for (int p = 0; p < 4; p++){
                ffma2_acc(A[cc][p], P[2*p+0], W01.x);
                ffma2_acc(A[cc][p], P[2*p+1], W01.y);
                ffma2_acc(A[cc][p], P[2*p+2], W23.x);
                ffma2_acc(A[cc][p], P[2*p+3], W23.y);
                ffma2_acc(A[cc][p], P[2*p+4], W4);
            }
        }
    }

    float* outp = g_buf1 + (size_t)b*CH*LSEQ;
#pragma unroll
    for (int cc = 0; cc < 8; cc++){
        float v[8];
#pragma unroll
        for (int p = 0; p < 4; p++) upk(A[cc][p], v[2*p], v[2*p+1]);
        int c = c0 + cc;
        *(float4*)(outp + c*LSEQ + l0)     = make_float4(v[0],v[1],v[2],v[3]);
        *(float4*)(outp + c*LSEQ + l0 + 4) = make_float4(v[4],v[5],v[6],v[7]);
        float s = 0.f, q = 0.f;
#pragma unroll
        for (int m = 0; m < 8; m++){ s += v[m]; q += v[m]*v[m]; }
        s = wred32(s); q = wred32(q);
        if (lane == 0){ redS[c] = s; redQ[c] = q; }   // channel owned by one warp
    }
    __syncthreads();
    if (t < 32){
        atomicAdd(&g_stat[0][0][t], (double)redS[t]);
        atomicAdd(&g_stat[0][1][t], (double)redQ[t]);
    }
}

// ---------------- K2/K3: bn+relu(in) -> conv (32->32, k=3, SAME)+bias ------
// One block = one sample HALF (128 L positions). grid = 2*BATCH.
// warp -> 8 output channels (broadcast weights); lane -> 4 L positions
__global__ __launch_bounds__(128, 4) void k_rbconv(int pass,
                                                const float* __restrict__ gam,
                                                const float* __restrict__ bet,
                                                const float* __restrict__ w,
                                                const float* __restrict__ cbias){
    const int b = blockIdx.x >> 1;
    const int lbase = (blockIdx.x & 1) * 128;
    const int t = threadIdx.x;
    const float* bufIn = (pass == 0) ? g_buf1 : g_buf2;
    float* bufOut = g_buf2;
    const int stIn = pass, stOut = pass + 1;

    extern __shared__ ull smu[];
    ull*   wd  = smu;                     // dup weights: ull[(i*32+c)*4 + k], 3072+1024 pad (k<3 live)
    float* sc  = (float*)(wd + 4096);     // 32
    float* sh  = sc + 32;                 // 32
    float* cbs = sh + 32;                 // 32
    float* xin = cbs + 32;                // 32*136 (xin[i][p] = xr(lbase-1+p), p<130 live)
    float* redS= xin + 32*136;            // 32
    float* redQ= redS + 32;               // 32

    if (t < 32){
        const double N = (double)BATCH * (double)LSEQ;
        double S = g_stat[stIn][0][t], Q = g_stat[stIn][1][t];
        double m = S / N, v = Q / N - m*m;
        double s = (double)gam[t] / sqrt(v + EPSBN);
        sc[t] = (float)s;
        sh[t] = (float)((double)bet[t] - m*s);
        cbs[t] = cbias[t];
    }
    for (int idx = t; idx < 32*32*4; idx += 128){
        int i = idx >> 7, rem = idx & 127, c = rem >> 2, k = rem & 3;
        float v = (k < 3) ? w[c*96 + i*3 + k] : 0.f;
        ((float2*)wd)[idx] = make_float2(v, v);
    }
    __syncthreads();

    const float* inp = bufIn + (size_t)b*CH*LSEQ;
    for (int idx = t; idx < 32*136; idx += 128){
        int i = idx >> 7;                     // idx/136 is wrong; compute properly below
        i = idx / 136;
        int p = idx - i*136;
        int l = lbase - 1 + p;
        float val = 0.f;
        if (p < 130 && l >= 0 && l < LSEQ){
            float y = inp[i*LSEQ + l];
            val = fmaxf(sc[i]*y + sh[i], 0.f);
        }
        xin[idx] = val;
    }
    __syncthreads();

    const int wrp = t >> 5, lane = t & 31;
    const int c0 = wrp*8, l0 = lane*4;        // local L offset within [0,128)

    ull A[8][2];
#pragma unroll
    for (int cc = 0; cc < 8; cc++){
        float cb = cbs[c0 + cc];
        A[cc][0] = pk(cb, cb);
        A[cc][1] = pk(cb, cb);
    }

#pragma unroll 4
    for (int i = 0; i < 32; i++){
        const float* xb = xin + i*136 + l0;   // xb[0] = xr_{lbase+l0-1}
        float4 u0 = *(const float4*)(xb);
        float2 u1 = *(const float2*)(xb + 4);
        float xm[6] = {u0.x,u0.y,u0.z,u0.w, u1.x,u1.y};
        ull P[5];
#pragma unroll
        for (int m = 0; m < 5; m++) P[m] = pk(xm[m], xm[m+1]);    // (xr_{l0+m-1}, xr_{l0+m})
        const ull* wp = wd + (i*32 + c0)*4;
#pragma unroll
        for (int cc = 0; cc < 8; cc++){
            ulonglong2 W01 = *(const ulonglong2*)(wp + cc*4);
            ull W2 = wp[cc*4 + 2];
#pragma unroll
            for (int j = 0; j < 2; j++){
                ffma2_acc(A[cc][j], P[2*j+0], W01.x);
                ffma2_acc(A[cc][j], P[2*j+1], W01.y);
                ffma2_acc(A[cc][j], P[2*j+2], W2);
            }
        }
    }

    float* outp = bufOut + (size_t)b*CH*LSEQ + lbase;
#pragma unroll
    for (int cc = 0; cc < 8; cc++){
        float v[4];
        upk(A[cc][0], v[0], v[1]);
        upk(A[cc][1], v[2], v[3]);
        int c = c0 + cc;
        *(float4*)(outp + c*LSEQ + l0) = make_float4(v[0],v[1],v[2],v[3]);
        float s = 0.f, q = 0.f;
#pragma unroll
        for (int m = 0; m < 4; m++){ s += v[m]; q += v[m]*v[m]; }
        s = wred32(s); q = wred32(q);
        if (lane == 0){ redS[c] = s; redQ[c] = q; }
    }
    __syncthreads();
    if (t < 32){
        atomicAdd(&g_stat[stOut][0][t], (double)redS[t]);
        atomicAdd(&g_stat[stOut][1][t], (double)redQ[t]);
    }
}

// ---------------- K4: bn0+relu, bn2, residual+relu, mean-pool, linear+tanh -
__global__ __launch_bounds__(256) void k_pool_ctx(const float* __restrict__ gamma1,
                                                  const float* __restrict__ beta1,
                                                  const float* __restrict__ gamma3,
                                                  const float* __restrict__ beta3,
                                                  const float* __restrict__ lin_w,
                                                  const float* __restrict__ lin_b){
    const int b = blockIdx.x;
    const int t = threadIdx.x;
    __shared__ float sc0[32], sh0[32], sc2[32], sh2[32];
    __shared__ float red[32][8];
    __shared__ float pooled[32];

    if (t < 32){
        const double N = (double)BATCH * (double)LSEQ;
        { double S = g_stat[0][0][t], Q = g_stat[0][1][t];
          double m = S/N, v = Q/N - m*m;
          double s = (double)gamma1[t] / sqrt(v + EPSBN);
          sc0[t] = (float)s; sh0[t] = (float)((double)beta1[t] - m*s); }
        { double S = g_stat[2][0][t], Q = g_stat[2][1][t];
          double m = S/N, v = Q/N - m*m;
          double s = (double)gamma3[t] / sqrt(v + EPSBN);
          sc2[t] = (float)s; sh2[t] = (float)((double)beta3[t] - m*s); }
    }
    __syncthreads();

    const float* p1 = g_buf1 + (size_t)b*CH*LSEQ;
    const float* p2 = g_buf2 + (size_t)b*CH*LSEQ;
    const int wid = t >> 5, lane = t & 31;
#pragma unroll 1
    for (int c = 0; c < 32; c++){
        float y1 = p1[c*LSEQ + t];
        float h2 = p2[c*LSEQ + t];
        float x1 = fmaxf(sc0[c]*y1 + sh0[c], 0.f);
        float x2 = fmaxf(sc2[c]*h2 + sh2[c] + x1, 0.f);
        float s = wred32(x2);
        if (lane == 0) red[c][wid] = s;
    }
    __syncthreads();
    if (t < 32){
        float s = 0.f;
#pragma unroll
        for (int wI = 0; wI < 8; wI++) s += red[t][wI];
        pooled[t] = s * (1.f/(float)LSEQ);
    }
    __syncthreads();
    if (t < 64){
        float acc = lin_b[t];
#pragma unroll
        for (int c = 0; c < 32; c++) acc += pooled[c]*lin_w[c*64 + t];
        g_ctx[(size_t)b*64 + t] = tanhf(acc);
    }
}

// ---------------- K5: 10 coupling layers, 64 rows per block, all in smem ---
__global__ __launch_bounds__(256) void k_coupling(const float* __restrict__ zin,
                                                  const float* __restrict__ W1,
                                                  const float* __restrict__ B1,
                                                  const float* __restrict__ W2,
                                                  const float* __restrict__ B2,
                                                  const float* __restrict__ W3,
                                                  const float* __restrict__ B3,
                                                  float* __restrict__ outp){
    const int t = threadIdx.x;
    const int rowBase = blockIdx.x * 64;
    extern __shared__ float sm[];
    float* nin = sm;                 // 64*76  (cols 0..8 = z*mask, 9..72 = ctx)
    float* hA  = nin + 64*76;        // 64*132
    float* hB  = hA  + 64*132;       // 64*132
    float* zz  = hB  + 64*132;       // 64*12
    float* ob  = zz  + 64*12;        // 64*20
    float* ldv = ob  + 64*20;        // 64

    for (int idx = t; idx < 64*9; idx += 256){
        int r = idx/9, j = idx - r*9;
        zz[r*12 + j] = zin[(size_t)(rowBase + r)*9 + j];
    }
    for (int idx = t; idx < 64*64; idx += 256){
        int r = idx >> 6, j = idx & 63;
        nin[r*76 + 9 + j] = g_ctx[(size_t)(rowBase + r)*64 + j];
    }
    if (t < 64) ldv[t] = 0.f;
    __syncthreads();

    const int jc = t & 31;           // 4 output columns: 4*jc .. 4*jc+3
    const int r0 = (t >> 5) * 8;     // 8 rows per warp

    for (int layer = 0; layer < 10; ++layer){
        if (t < 64){
#pragma unroll
            for (int j = 0; j < 9; j++){
                float m = (((j + layer) & 1) == 0) ? 1.f : 0.f;
                nin[t*76 + j] = zz[t*12 + j] * m;
            }
        }
        __syncthreads();

        // GEMM1: hA = relu(nin[64x73] @ W1[73x128] + b1)  (packed f32x2)
        {
            const float* Wl = W1 + (size_t)layer*73*128;
            float4 bb = *(const float4*)(B1 + layer*128 + 4*jc);
            ull acc[8][2];
#pragma unroll
            for (int r = 0; r < 8; r++){ acc[r][0] = pk(bb.x, bb.y); acc[r][1] = pk(bb.z, bb.w); }
#pragma unroll 2
            for (int i = 0; i < 73; i++){
                ulonglong2 wv = *(const ulonglong2*)(Wl + i*128 + 4*jc);
#pragma unroll
                for (int r = 0; r < 8; r++){
                    float x = nin[(r0 + r)*76 + i];
                    ull xx = pk(x, x);
                    ffma2_acc(acc[r][0], xx, wv.x);
                    ffma2_acc(acc[r][1], xx, wv.y);
                }
            }
#pragma unroll
            for (int r = 0; r < 8; r++){
                float v0,v1,v2,v3;
                upk(acc[r][0], v0, v1); upk(acc[r][1], v2, v3);
                *(float4*)(hA + (r0 + r)*132 + 4*jc) =
                    make_float4(fmaxf(v0,0.f), fmaxf(v1,0.f), fmaxf(v2,0.f), fmaxf(v3,0.f));
            }
        }
        __syncthreads();

        // GEMM2: hB = relu(hA[64x128] @ W2[128x128] + b2)  (packed f32x2)
        {
            const float* Wl = W2 + (size_t)layer*128*128;
            float4 bb = *(const float4*)(B2 + layer*128 + 4*jc);
            ull acc[8][2];
#pragma unroll
            for (int r = 0; r < 8; r++){ acc[r][0] = pk(bb.x, bb.y); acc[r][1] = pk(bb.z, bb.w); }
#pragma unroll 2
            for (int i = 0; i < 128; i++){
                ulonglong2 wv = *(const ulonglong2*)(Wl + i*128 + 4*jc);
#pragma unroll
                for (int r = 0; r < 8; r++){
                    float x = hA[(r0 + r)*132 + i];
                    ull xx = pk(x, x);
                    ffma2_acc(acc[r][0], xx, wv.x);
                    ffma2_acc(acc[r][1], xx, wv.y);
                }
            }
#pragma unroll
            for (int r = 0; r < 8; r++){
                float v0,v1,v2,v3;
                upk(acc[r][0], v0, v1); upk(acc[r][1], v2, v3);
                *(float4*)(hB + (r0 + r)*132 + 4*jc) =
                    make_float4(fmaxf(v0,0.f), fmaxf(v1,0.f), fmaxf(v2,0.f), fmaxf(v3,0.f));
            }
        }
        __syncthreads();

        // GEMM3: ob = hB[64x128] @ W3[128x18] + b3
        {
            const float* Wl = W3 + (size_t)layer*128*18;
            const int r = t >> 2, q = t & 3;
            float acc[5] = {0.f,0.f,0.f,0.f,0.f};
#pragma unroll 2
            for (int i = 0; i < 128; i++){
                float x = hB[r*132 + i];
#pragma unroll
                for (int k = 0; k < 5; k++){
                    int j = q + 4*k;
                    if (j < 18) acc[k] = fmaf(x, __ldg(Wl + i*18 + j), acc[k]);
                }
            }
#pragma unroll
            for (int k = 0; k < 5; k++){
                int j = q + 4*k;
                if (j < 18) ob[r*20 + j] = acc[k] + B3[layer*18 + j];
            }
        }
        __syncthreads();

        // per-row flow update
        if (t < 64){
            float ldl = ldv[t];
#pragma unroll
            for (int j = 0; j < 9; j++){
                if (((j + layer) & 1) != 0){     // unmasked dims
                    float s  = tanhf(ob[t*20 + j]);
                    float tt = ob[t*20 + 9 + j];
                    zz[t*12 + j] = zz[t*12 + j]*expf(s) + tt;
                    ldl += s;
                }
            }
            ldv[t] = ldl;
        }
        __syncthreads();
    }

    if (t < 64){
        float lp = 0.f;
#pragma unroll
        for (int j = 0; j < 9; j++){
            float z = zz[t*12 + j];
            lp += LOG2PI + z*z;
        }
        outp[rowBase + t] = ldv[t] - 0.5f*lp;
    }
}

// ---------------- launch ----------------------------------------------------
extern "C" void kernel_launch(void* const* d_in, const int* in_sizes, int n_in,
                              void* d_out, int out_size){
    const float* inputs  = (const float*)d_in[0];
    const float* curve   = (const float*)d_in[1];
    const float* conv1_w = (const float*)d_in[2];
    const float* conv1_b = (const float*)d_in[3];
    const float* bn1_g   = (const float*)d_in[4];
    const float* bn1_b   = (const float*)d_in[5];
    const float* rb_w1   = (const float*)d_in[6];
    const float* rb_b1   = (const float*)d_in[7];
    const float* rb_g1   = (const float*)d_in[8];
    const float* rb_be1  = (const float*)d_in[9];
    const float* rb_w2   = (const float*)d_in[10];
    const float* rb_b2   = (const float*)d_in[11];
    const float* rb_g2   = (const float*)d_in[12];
    const float* rb_be2  = (const float*)d_in[13];
    const float* lin_w   = (const float*)d_in[14];
    const float* lin_b   = (const float*)d_in[15];
    const float* W1      = (const float*)d_in[16];
    const float* B1      = (const float*)d_in[17];
    const float* W2      = (const float*)d_in[18];
    const float* B2      = (const float*)d_in[19];
    const float* W3      = (const float*)d_in[20];
    const float* B3      = (const float*)d_in[21];
    float* out = (float*)d_out;

    const int smem1 = 1024*8 + (32 + 4*272 + 32 + 32) * 4;
    const int smemR = 4096*8 + (96 + 32*136 + 64) * 4;
    const int smemC = (64*76 + 64*132*2 + 64*12 + 64*20 + 64) * 4;

    cudaFuncSetAttribute(k_conv1,    cudaFuncAttributeMaxDynamicSharedMemorySize, smem1);
    cudaFuncSetAttribute(k_rbconv,   cudaFuncAttributeMaxDynamicSharedMemorySize, smemR);
    cudaFuncSetAttribute(k_coupling, cudaFuncAttributeMaxDynamicSharedMemorySize, smemC);

    k_init_stats<<<1, 192>>>();
    k_conv1<<<BATCH, 128, smem1>>>(curve, conv1_w, conv1_b);
    k_rbconv<<<BATCH*2, 128, smemR>>>(0, bn1_g, bn1_b, rb_w1, rb_b1);
    k_rbconv<<<BATCH*2, 128, smemR>>>(1, rb_g1, rb_be1, rb_w2, rb_b2);
    k_pool_ctx<<<BATCH, 256>>>(bn1_g, bn1_b, rb_g2, rb_be2, lin_w, lin_b);
    k_coupling<<<BATCH/64, 256, smemC>>>(inputs, W1, B1, W2, B2, W3, B3, out);
}